// round 7
// baseline (speedup 1.0000x reference)
#include <cuda_runtime.h>
#include <cuda_bf16.h>
#include <math.h>

// Problem constants
#define BB 16      // batch
#define TT 128     // seq len
#define HH 512     // hidden
#define VV 32000   // vocab
#define G3 1536    // 3*H
#define BOS 1

// ---------------- scratch (device globals; no allocation) ----------------
__device__ float g_x[BB * TT * HH];              // relu(emb[inputs]) rows r = t*16+b (4 MB)
__device__ float g_xproj[TT * BB * G3];          // [T][B][3H]                       (12.6 MB)
__device__ float g_h[2][BB * HH];                // double-buffered hidden state
__device__ float g_logits[(size_t)BB * TT * VV]; // [2048][32000]                    (262 MB)
__device__ __nv_bfloat16 g_Ahi[BB * TT * HH];    // gru_out hi, rows r = b*TT+t (2 MB)
__device__ __nv_bfloat16 g_Alo[BB * TT * HH];    // gru_out lo                  (2 MB)
__device__ __nv_bfloat16 g_Bhi[(size_t)VV * HH]; // w_out bf16  (32.8 MB)

// ---------------- packed f32x2 helpers (Blackwell FFMA2) ----------------
__device__ __forceinline__ unsigned long long dup_f32x2(float x) {
    unsigned long long r;
    asm("mov.b64 %0, {%1, %1};" : "=l"(r) : "f"(x));
    return r;
}
__device__ __forceinline__ void fma_f32x2(unsigned long long& acc,
                                          unsigned long long a,
                                          unsigned long long b) {
    asm("fma.rn.f32x2 %0, %1, %2, %0;" : "+l"(acc) : "l"(a), "l"(b));
}
__device__ __forceinline__ void unpack_f32x2(unsigned long long v, float& lo, float& hi) {
    asm("mov.b64 {%0, %1}, %2;" : "=f"(lo), "=f"(hi) : "l"(v));
}

union F4U2 { float4 f4; unsigned long long u2[2]; };

// ---------------- kernel 1: embedding + ReLU ----------------
__global__ void embed_relu_kernel(const int* __restrict__ tgt,
                                  const float* __restrict__ emb) {
    int r = blockIdx.x;            // r = t*16 + b
    int t = r >> 4;
    int b = r & 15;
    int idx = (t == 0) ? BOS : tgt[b * TT + (t - 1)];
    const float4* e = (const float4*)(emb + (size_t)idx * HH);
    float4 v = e[threadIdx.x];
    v.x = fmaxf(v.x, 0.f); v.y = fmaxf(v.y, 0.f);
    v.z = fmaxf(v.z, 0.f); v.w = fmaxf(v.w, 0.f);
    ((float4*)(g_x + (size_t)r * HH))[threadIdx.x] = v;
}

// ---------------- fp32 tiled SGEMM (FFMA2) for x_proj ----------------
#define BM 128
#define BN 128
#define BK 8
__global__ __launch_bounds__(256, 2) void gemm_bias_kernel(
    const float* __restrict__ A, const float* __restrict__ B,
    const float* __restrict__ bias, float* __restrict__ C,
    int M, int N, int K) {
    __shared__ float As[2][BK][BM + 4];
    __shared__ float Bs[2][BK][BN + 4];

    int tid = threadIdx.x;
    int bm = blockIdx.y, bn = blockIdx.x;
    int tm = tid >> 4;
    int tn = tid & 15;

    int lrow = tid >> 1;
    int lcol = (tid & 1) * 4;
    const float* Ag = A + ((size_t)(bm * BM + lrow)) * K + lcol;
    const float* Bg = B + ((size_t)(bn * BN + lrow)) * K + lcol;

    unsigned long long acc2[8][4];
#pragma unroll
    for (int i = 0; i < 8; i++)
#pragma unroll
        for (int p = 0; p < 4; p++) acc2[i][p] = 0ull;

    {
        float4 a = *(const float4*)Ag;
        float4 b = *(const float4*)Bg;
        As[0][lcol + 0][lrow] = a.x; As[0][lcol + 1][lrow] = a.y;
        As[0][lcol + 2][lrow] = a.z; As[0][lcol + 3][lrow] = a.w;
        Bs[0][lcol + 0][lrow] = b.x; Bs[0][lcol + 1][lrow] = b.y;
        Bs[0][lcol + 2][lrow] = b.z; Bs[0][lcol + 3][lrow] = b.w;
    }
    __syncthreads();

    int KT = K / BK;
    int buf = 0;
    for (int kt = 0; kt < KT; kt++) {
        float4 an, bn4;
        bool more = (kt + 1 < KT);
        if (more) {
            an  = *(const float4*)(Ag + (kt + 1) * BK);
            bn4 = *(const float4*)(Bg + (kt + 1) * BK);
        }
#pragma unroll
        for (int k = 0; k < BK; k++) {
            float4 a0 = *(const float4*)&As[buf][k][tm * 8];
            float4 a1 = *(const float4*)&As[buf][k][tm * 8 + 4];
            F4U2 b0, b1;
            b0.f4 = *(const float4*)&Bs[buf][k][tn * 8];
            b1.f4 = *(const float4*)&Bs[buf][k][tn * 8 + 4];
            unsigned long long bp[4] = {b0.u2[0], b0.u2[1], b1.u2[0], b1.u2[1]};
            float av[8] = {a0.x, a0.y, a0.z, a0.w, a1.x, a1.y, a1.z, a1.w};
#pragma unroll
            for (int i = 0; i < 8; i++) {
                unsigned long long ad = dup_f32x2(av[i]);
#pragma unroll
                for (int p = 0; p < 4; p++)
                    fma_f32x2(acc2[i][p], ad, bp[p]);
            }
        }
        if (more) {
            int nb = buf ^ 1;
            As[nb][lcol + 0][lrow] = an.x;  As[nb][lcol + 1][lrow] = an.y;
            As[nb][lcol + 2][lrow] = an.z;  As[nb][lcol + 3][lrow] = an.w;
            Bs[nb][lcol + 0][lrow] = bn4.x; Bs[nb][lcol + 1][lrow] = bn4.y;
            Bs[nb][lcol + 2][lrow] = bn4.z; Bs[nb][lcol + 3][lrow] = bn4.w;
        }
        __syncthreads();
        buf ^= 1;
    }

    int ncol = bn * BN + tn * 8;
    float4 bias0 = *(const float4*)(bias + ncol);
    float4 bias1 = *(const float4*)(bias + ncol + 4);
#pragma unroll
    for (int i = 0; i < 8; i++) {
        int row = bm * BM + tm * 8 + i;
        float* Cp = C + (size_t)row * N + ncol;
        float a01l, a01h, a23l, a23h, a45l, a45h, a67l, a67h;
        unpack_f32x2(acc2[i][0], a01l, a01h);
        unpack_f32x2(acc2[i][1], a23l, a23h);
        unpack_f32x2(acc2[i][2], a45l, a45h);
        unpack_f32x2(acc2[i][3], a67l, a67h);
        float4 c0, c1;
        c0.x = a01l + bias0.x; c0.y = a01h + bias0.y;
        c0.z = a23l + bias0.z; c0.w = a23h + bias0.w;
        c1.x = a45l + bias1.x; c1.y = a45h + bias1.y;
        c1.z = a67l + bias1.z; c1.w = a67h + bias1.w;
        *(float4*)(Cp)     = c0;
        *(float4*)(Cp + 4) = c1;
    }
}

// ---------------- convert fp32 -> bf16 (hi only) for w_out ----------------
__global__ void convert_bf16_kernel(const float* __restrict__ src,
                                    __nv_bfloat16* __restrict__ hi, int n4) {
    int i = blockIdx.x * blockDim.x + threadIdx.x;
    if (i >= n4) return;
    float4 v = ((const float4*)src)[i];
    __nv_bfloat162* h2 = (__nv_bfloat162*)hi;
    h2[2 * i]     = __nv_bfloat162{__float2bfloat16_rn(v.x), __float2bfloat16_rn(v.y)};
    h2[2 * i + 1] = __nv_bfloat162{__float2bfloat16_rn(v.z), __float2bfloat16_rn(v.w)};
}

// ---------------- bf16 mma.sync logits GEMM (2-term split) ----------------
// C[2048,32000] = (Ahi + Alo) * Bhi^T + bias ; dropped Ahi*Blo residual ~7e-5 abs.
#define LBM 128
#define LBN 128
#define LBK 32
#define LSTR (LBK + 8)                 // padded bf16 row stride (80B rows -> conflict-free ldmatrix)
#define LSTAGE (LBM * LSTR)            // bf16 elems per stage

__device__ __forceinline__ void ldsm_x4(unsigned& r0, unsigned& r1, unsigned& r2, unsigned& r3,
                                        unsigned addr) {
    asm volatile("ldmatrix.sync.aligned.m8n8.x4.shared.b16 {%0,%1,%2,%3}, [%4];\n"
                 : "=r"(r0), "=r"(r1), "=r"(r2), "=r"(r3) : "r"(addr));
}
__device__ __forceinline__ void mma_bf16(float& c0, float& c1, float& c2, float& c3,
                                         unsigned a0, unsigned a1, unsigned a2, unsigned a3,
                                         unsigned b0, unsigned b1) {
    asm volatile("mma.sync.aligned.m16n8k16.row.col.f32.bf16.bf16.f32 "
                 "{%0,%1,%2,%3},{%4,%5,%6,%7},{%8,%9},{%0,%1,%2,%3};\n"
                 : "+f"(c0), "+f"(c1), "+f"(c2), "+f"(c3)
                 : "r"(a0), "r"(a1), "r"(a2), "r"(a3), "r"(b0), "r"(b1));
}

__global__ __launch_bounds__(256, 2) void mma_logits_kernel(
    const __nv_bfloat16* __restrict__ A_hi, const __nv_bfloat16* __restrict__ A_lo,
    const __nv_bfloat16* __restrict__ B_hi,
    const float* __restrict__ bias, float* __restrict__ C) {
    __shared__ __nv_bfloat16 As[2][LBM][LSTR];
    __shared__ __nv_bfloat16 Bs[2][LBN][LSTR];

    const int tid = threadIdx.x;
    const int bm = blockIdx.y, bn = blockIdx.x;
    const int warp = tid >> 5, lane = tid & 31;
    const int wm = warp >> 2, wn = warp & 3;      // 2 x 4 warps, tile 64 x 32

    const int lrow = tid >> 1;
    const int lhalf = (tid & 1) * 16;
    const size_t Aoff = (size_t)(bm * LBM + lrow) * HH + lhalf;
    const size_t Boff = (size_t)(bn * LBN + lrow) * HH + lhalf;

    const __nv_bfloat16* Asrc[2] = {A_hi, A_lo};

    float acc[4][4][4];
#pragma unroll
    for (int i = 0; i < 4; i++)
#pragma unroll
        for (int j = 0; j < 4; j++)
#pragma unroll
            for (int c = 0; c < 4; c++) acc[i][j][c] = 0.f;

    const int q = lane >> 3, rr = lane & 7;
    unsigned as_base = (unsigned)__cvta_generic_to_shared(&As[0][0][0]);
    unsigned bs_base = (unsigned)__cvta_generic_to_shared(&Bs[0][0][0]);
    unsigned a_addr0 = as_base + (unsigned)(((wm * 64 + (q & 1) * 8 + rr) * LSTR + (q >> 1) * 8) * 2);
    unsigned b_addr0 = bs_base + (unsigned)(((wn * 32 + (q >> 1) * 8 + rr) * LSTR + (q & 1) * 8) * 2);

    {
        uint4 a0 = *(const uint4*)(Asrc[0] + Aoff);
        uint4 a1 = *(const uint4*)(Asrc[0] + Aoff + 8);
        uint4 b0 = *(const uint4*)(B_hi + Boff);
        uint4 b1 = *(const uint4*)(B_hi + Boff + 8);
        *(uint4*)&As[0][lrow][lhalf]     = a0;
        *(uint4*)&As[0][lrow][lhalf + 8] = a1;
        *(uint4*)&Bs[0][lrow][lhalf]     = b0;
        *(uint4*)&Bs[0][lrow][lhalf + 8] = b1;
    }
    __syncthreads();

    const int KTOT = 2 * (HH / LBK);   // 32
    int buf = 0;
    for (int kt = 0; kt < KTOT; kt++) {
        uint4 pa0, pa1, pb0, pb1;
        bool more = (kt + 1 < KTOT);
        if (more) {
            int seg = (kt + 1) >> 4;               // 0 or 1
            int kk = ((kt + 1) & 15) * LBK;
            pa0 = *(const uint4*)(Asrc[seg] + Aoff + kk);
            pa1 = *(const uint4*)(Asrc[seg] + Aoff + kk + 8);
            pb0 = *(const uint4*)(B_hi + Boff + kk);
            pb1 = *(const uint4*)(B_hi + Boff + kk + 8);
        }
        unsigned bufoff = (unsigned)(buf * LSTAGE * 2);
#pragma unroll
        for (int ks = 0; ks < 2; ks++) {
            unsigned af[4][4], bfr[2][4];
#pragma unroll
            for (int mf = 0; mf < 4; mf++)
                ldsm_x4(af[mf][0], af[mf][1], af[mf][2], af[mf][3],
                        a_addr0 + bufoff + (unsigned)(mf * 16 * LSTR * 2 + ks * 32));
#pragma unroll
            for (int nf2 = 0; nf2 < 2; nf2++)
                ldsm_x4(bfr[nf2][0], bfr[nf2][1], bfr[nf2][2], bfr[nf2][3],
                        b_addr0 + bufoff + (unsigned)(nf2 * 16 * LSTR * 2 + ks * 32));
#pragma unroll
            for (int mf = 0; mf < 4; mf++)
#pragma unroll
                for (int nf = 0; nf < 4; nf++)
                    mma_bf16(acc[mf][nf][0], acc[mf][nf][1], acc[mf][nf][2], acc[mf][nf][3],
                             af[mf][0], af[mf][1], af[mf][2], af[mf][3],
                             bfr[nf >> 1][(nf & 1) * 2], bfr[nf >> 1][(nf & 1) * 2 + 1]);
        }
        if (more) {
            int nb = buf ^ 1;
            *(uint4*)&As[nb][lrow][lhalf]     = pa0;
            *(uint4*)&As[nb][lrow][lhalf + 8] = pa1;
            *(uint4*)&Bs[nb][lrow][lhalf]     = pb0;
            *(uint4*)&Bs[nb][lrow][lhalf + 8] = pb1;
        }
        __syncthreads();
        buf ^= 1;
    }

    const int rbase = bm * LBM + wm * 64 + (lane >> 2);
    const int cb = bn * LBN + wn * 32 + 2 * (lane & 3);
#pragma unroll
    for (int mf = 0; mf < 4; mf++) {
#pragma unroll
        for (int nf = 0; nf < 4; nf++) {
            int col = cb + nf * 8;
            float bx = bias[col], by = bias[col + 1];
            int r0 = rbase + mf * 16;
            float2 v0 = {acc[mf][nf][0] + bx, acc[mf][nf][1] + by};
            float2 v1 = {acc[mf][nf][2] + bx, acc[mf][nf][3] + by};
            *(float2*)(C + (size_t)r0 * VV + col)       = v0;
            *(float2*)(C + (size_t)(r0 + 8) * VV + col) = v1;
        }
    }
}

// ---------------- kernel: init hidden from encoder_hidden ----------------
__global__ void hinit_kernel(const float* __restrict__ eh) {
    int i = blockIdx.x * blockDim.x + threadIdx.x;   // 2048 float4
    ((float4*)g_h[0])[i] = ((const float4*)eh)[i];
}

// ---------------- persistent GRU scan (one launch, 128 co-resident blocks) ----------------
#define GRUBLOCKS 128
#define HPAD 516
__device__ unsigned g_bar_count;               // returns to 0 after every barrier
__device__ volatile unsigned g_bar_gen;        // monotonically increasing generation

__device__ __forceinline__ void grid_barrier_128() {
    __syncthreads();
    if (threadIdx.x == 0) {
        __threadfence();                       // release my block's writes
        unsigned gen = g_bar_gen;              // read BEFORE arriving
        if (atomicAdd(&g_bar_count, 1u) == GRUBLOCKS - 1) {
            g_bar_count = 0;
            __threadfence();                   // count reset visible before release
            g_bar_gen = gen + 1;
        } else {
            // capped spin: a barrier bug fails with wrong output, not a hang
            for (long long s = 0; g_bar_gen == gen && s < 4000000LL; s++) {}
        }
        __threadfence();                       // acquire other blocks' writes
    }
    __syncthreads();
}

__global__ __launch_bounds__(256, 1) void gru_persistent_kernel(
    const float* __restrict__ w_hh, const float* __restrict__ b_hh) {
    __shared__ float h_s[BB * HPAD];
    __shared__ float hp_s[192];
    const int tid = threadIdx.x;
    const int jbase = blockIdx.x * 4;

    // per-thread invariants for the dot phase (w_hh rows stay L1-resident across steps)
    const int db = tid & 15;            // batch (dot phase)
    const int didx = tid >> 4;          // 0..11 when tid<192 : gate*4 + col
    const int drow = (didx >> 2) * HH + jbase + (didx & 3);
    const float4* w4 = (const float4*)(w_hh + (size_t)drow * HH);
    const float bh = (tid < 192) ? b_hh[drow] : 0.f;

    for (int t = 0; t < TT; t++) {
        const float* h_in = g_h[t & 1];
        float* h_out = g_h[(t + 1) & 1];

        // load h [16,512] into padded smem (L2-only loads: avoid stale L1 across barrier)
        for (int i = tid; i < BB * (HH / 4); i += 256) {
            int b = i >> 7;
            int k4 = i & 127;
            float4 v = __ldcg(((const float4*)(h_in + b * HH)) + k4);
            ((float4*)(h_s + b * HPAD))[k4] = v;
        }
        __syncthreads();

        if (tid < 192) {
            const float4* h4 = (const float4*)(h_s + db * HPAD);
            float s0 = 0.f, s1 = 0.f, s2 = 0.f, s3 = 0.f;
#pragma unroll 8
            for (int k = 0; k < HH / 4; k++) {
                float4 w = w4[k];
                float4 h = h4[k];
                s0 += w.x * h.x; s1 += w.y * h.y;
                s2 += w.z * h.z; s3 += w.w * h.w;
            }
            hp_s[didx * 16 + db] = (s0 + s1) + (s2 + s3) + bh;
        }
        __syncthreads();

        if (tid < 64) {
            int b = tid & 15;
            int jc = tid >> 4;
            int j = jbase + jc;
            const float* xp = g_xproj + ((size_t)(t * BB + b)) * G3;
            float xr = xp[j], xz = xp[HH + j], xn = xp[2 * HH + j];
            float hr = hp_s[(0 * 4 + jc) * 16 + b];
            float hz = hp_s[(1 * 4 + jc) * 16 + b];
            float hn = hp_s[(2 * 4 + jc) * 16 + b];
            float r = 1.f / (1.f + __expf(-(xr + hr)));
            float z = 1.f / (1.f + __expf(-(xz + hz)));
            float n = tanhf(xn + r * hn);
            float hprev = h_s[b * HPAD + j];
            float hnew = (1.f - z) * n + z * hprev;
            h_out[b * HH + j] = hnew;
            size_t ai = ((size_t)(b * TT + t)) * HH + j;
            __nv_bfloat16 hi = __float2bfloat16_rn(hnew);
            g_Ahi[ai] = hi;
            g_Alo[ai] = __float2bfloat16_rn(hnew - __bfloat162float(hi));
        }
        grid_barrier_128();   // all reads of buf[t&1] complete before anyone writes it at t+1
    }
}

// ---------------- kernel: row-wise log-softmax ----------------
__global__ void logsoftmax_kernel(const float* __restrict__ logits,
                                  float* __restrict__ out) {
    int r = blockIdx.x;
    const float4* x4 = (const float4*)(logits + (size_t)r * VV);
    float4* o4 = (float4*)(out + (size_t)r * VV);
    int tid = threadIdx.x;
    const int NV4 = VV / 4;

    float m = -INFINITY, s = 0.f;
    for (int c = tid; c < NV4; c += 256) {
        float4 v = x4[c];
        float mn;
        mn = fmaxf(m, v.x); s = s * __expf(m - mn) + __expf(v.x - mn); m = mn;
        mn = fmaxf(m, v.y); s = s * __expf(m - mn) + __expf(v.y - mn); m = mn;
        mn = fmaxf(m, v.z); s = s * __expf(m - mn) + __expf(v.z - mn); m = mn;
        mn = fmaxf(m, v.w); s = s * __expf(m - mn) + __expf(v.w - mn); m = mn;
    }
    __shared__ float ms[256], ss[256];
    ms[tid] = m; ss[tid] = s;
    __syncthreads();
    for (int off = 128; off > 0; off >>= 1) {
        if (tid < off) {
            float m2 = ms[tid + off], s2 = ss[tid + off];
            float mn = fmaxf(ms[tid], m2);
            ss[tid] = ss[tid] * __expf(ms[tid] - mn) + s2 * __expf(m2 - mn);
            ms[tid] = mn;
        }
        __syncthreads();
    }
    float lse = ms[0] + __logf(ss[0]);
    for (int c = tid; c < NV4; c += 256) {
        float4 v = x4[c];
        v.x -= lse; v.y -= lse; v.z -= lse; v.w -= lse;
        o4[c] = v;
    }
}

// ---------------- kernel: copy final hidden to tail of output ----------------
__global__ void copy_hidden_kernel(float* __restrict__ dst) {
    int i = blockIdx.x * blockDim.x + threadIdx.x;   // 2048 float4
    ((float4*)dst)[i] = ((const float4*)g_h[0])[i];  // T=128 even -> final state in buf 0
}

// ---------------- launcher ----------------
// inputs: 0 encoder_output (unused), 1 encoder_hidden, 2 tgt_tensor, 3 emb,
// 4 w_ih, 5 b_ih, 6 w_hh, 7 b_hh, 8 w_out, 9 b_out
// output: log_probs [16,128,32000] fp32, then hidden [1,16,512] fp32
extern "C" void kernel_launch(void* const* d_in, const int* in_sizes, int n_in,
                              void* d_out, int out_size) {
    const float* encoder_hidden = (const float*)d_in[1];
    const int*   tgt            = (const int*)d_in[2];
    const float* emb            = (const float*)d_in[3];
    const float* w_ih           = (const float*)d_in[4];
    const float* b_ih           = (const float*)d_in[5];
    const float* w_hh           = (const float*)d_in[6];
    const float* b_hh           = (const float*)d_in[7];
    const float* w_out          = (const float*)d_in[8];
    const float* b_out          = (const float*)d_in[9];
    float* out = (float*)d_out;

    float *g_x_p, *g_xproj_p, *g_logits_p;
    __nv_bfloat16 *ahi, *alo, *bhi;
    cudaGetSymbolAddress((void**)&g_x_p, g_x);
    cudaGetSymbolAddress((void**)&g_xproj_p, g_xproj);
    cudaGetSymbolAddress((void**)&g_logits_p, g_logits);
    cudaGetSymbolAddress((void**)&ahi, g_Ahi);
    cudaGetSymbolAddress((void**)&alo, g_Alo);
    cudaGetSymbolAddress((void**)&bhi, g_Bhi);

    // 1. embedding + relu
    embed_relu_kernel<<<BB * TT, 128>>>(tgt, emb);

    // 2. x_proj = x @ w_ih^T + b_ih (fp32 — feeds recurrence)
    gemm_bias_kernel<<<dim3(G3 / BN, (BB * TT) / BM), 256>>>(
        g_x_p, w_ih, b_ih, g_xproj_p, BB * TT, G3, HH);

    // 3. convert w_out to bf16 (hi only; independent of scan)
    {
        int n4 = VV * HH / 4;
        convert_bf16_kernel<<<(n4 + 255) / 256, 256>>>(w_out, bhi, n4);
    }

    // 4. h0 <- encoder_hidden; persistent GRU scan (single launch)
    hinit_kernel<<<8, 256>>>(encoder_hidden);
    gru_persistent_kernel<<<GRUBLOCKS, 256>>>(w_hh, b_hh);

    // 5. logits via tensor cores (2-term bf16 split)
    mma_logits_kernel<<<dim3(VV / LBN, (BB * TT) / LBM), 256>>>(
        ahi, alo, bhi, b_out, g_logits_p);

    // 6. log_softmax -> output
    logsoftmax_kernel<<<BB * TT, 256>>>(g_logits_p, out);

    // 7. final hidden -> tail of output
    copy_hidden_kernel<<<8, 256>>>(out + (size_t)BB * TT * VV);
}

// round 12
// speedup vs baseline: 1.5856x; 1.5856x over previous
#include <cuda_runtime.h>
#include <cuda_bf16.h>
#include <math.h>

// Problem constants
#define BB 16      // batch
#define TT 128     // seq len
#define HH 512     // hidden
#define VV 32000   // vocab
#define G3 1536    // 3*H
#define BOS 1

// ---------------- scratch (device globals; no allocation) ----------------
__device__ float g_x[BB * TT * HH];              // relu(emb[inputs]) rows r = t*16+b (4 MB)
__device__ float g_xproj[TT * BB * G3];          // [T][B][3H]                       (12.6 MB)
__device__ float g_h[2][BB * HH];                // double-buffered hidden state
__device__ float g_logits[(size_t)BB * TT * VV]; // [2048][32000]                    (262 MB)
__device__ __nv_bfloat16 g_Ahi[BB * TT * HH];    // gru_out hi, rows r = b*TT+t (2 MB)
__device__ __nv_bfloat16 g_Alo[BB * TT * HH];    // gru_out lo                  (2 MB)
__device__ __nv_bfloat16 g_Bhi[(size_t)VV * HH]; // w_out bf16  (32.8 MB)

// ---------------- packed f32x2 helpers (Blackwell FFMA2) ----------------
__device__ __forceinline__ unsigned long long dup_f32x2(float x) {
    unsigned long long r;
    asm("mov.b64 %0, {%1, %1};" : "=l"(r) : "f"(x));
    return r;
}
__device__ __forceinline__ void fma_f32x2(unsigned long long& acc,
                                          unsigned long long a,
                                          unsigned long long b) {
    asm("fma.rn.f32x2 %0, %1, %2, %0;" : "+l"(acc) : "l"(a), "l"(b));
}
__device__ __forceinline__ void unpack_f32x2(unsigned long long v, float& lo, float& hi) {
    asm("mov.b64 {%0, %1}, %2;" : "=f"(lo), "=f"(hi) : "l"(v));
}

union F4U2 { float4 f4; unsigned long long u2[2]; };

// ---------------- cp.async helpers ----------------
__device__ __forceinline__ void cp_async16(unsigned smem_addr, const void* gptr) {
    asm volatile("cp.async.cg.shared.global [%0], [%1], 16;\n"
                 :: "r"(smem_addr), "l"(gptr));
}
__device__ __forceinline__ void cp_commit() {
    asm volatile("cp.async.commit_group;\n");
}
__device__ __forceinline__ void cp_wait0() {
    asm volatile("cp.async.wait_group 0;\n" ::: "memory");
}

// ---------------- kernel 1: embedding + ReLU ----------------
__global__ void embed_relu_kernel(const int* __restrict__ tgt,
                                  const float* __restrict__ emb) {
    int r = blockIdx.x;            // r = t*16 + b
    int t = r >> 4;
    int b = r & 15;
    int idx = (t == 0) ? BOS : tgt[b * TT + (t - 1)];
    const float4* e = (const float4*)(emb + (size_t)idx * HH);
    float4 v = e[threadIdx.x];
    v.x = fmaxf(v.x, 0.f); v.y = fmaxf(v.y, 0.f);
    v.z = fmaxf(v.z, 0.f); v.w = fmaxf(v.w, 0.f);
    ((float4*)(g_x + (size_t)r * HH))[threadIdx.x] = v;
}

// ---------------- fp32 tiled SGEMM (FFMA2) for x_proj ----------------
#define BM 128
#define BN 128
#define BK 8
__global__ __launch_bounds__(256, 2) void gemm_bias_kernel(
    const float* __restrict__ A, const float* __restrict__ B,
    const float* __restrict__ bias, float* __restrict__ C,
    int M, int N, int K) {
    __shared__ float As[2][BK][BM + 4];
    __shared__ float Bs[2][BK][BN + 4];

    int tid = threadIdx.x;
    int bm = blockIdx.y, bn = blockIdx.x;
    int tm = tid >> 4;
    int tn = tid & 15;

    int lrow = tid >> 1;
    int lcol = (tid & 1) * 4;
    const float* Ag = A + ((size_t)(bm * BM + lrow)) * K + lcol;
    const float* Bg = B + ((size_t)(bn * BN + lrow)) * K + lcol;

    unsigned long long acc2[8][4];
#pragma unroll
    for (int i = 0; i < 8; i++)
#pragma unroll
        for (int p = 0; p < 4; p++) acc2[i][p] = 0ull;

    {
        float4 a = *(const float4*)Ag;
        float4 b = *(const float4*)Bg;
        As[0][lcol + 0][lrow] = a.x; As[0][lcol + 1][lrow] = a.y;
        As[0][lcol + 2][lrow] = a.z; As[0][lcol + 3][lrow] = a.w;
        Bs[0][lcol + 0][lrow] = b.x; Bs[0][lcol + 1][lrow] = b.y;
        Bs[0][lcol + 2][lrow] = b.z; Bs[0][lcol + 3][lrow] = b.w;
    }
    __syncthreads();

    int KT = K / BK;
    int buf = 0;
    for (int kt = 0; kt < KT; kt++) {
        float4 an, bn4;
        bool more = (kt + 1 < KT);
        if (more) {
            an  = *(const float4*)(Ag + (kt + 1) * BK);
            bn4 = *(const float4*)(Bg + (kt + 1) * BK);
        }
#pragma unroll
        for (int k = 0; k < BK; k++) {
            float4 a0 = *(const float4*)&As[buf][k][tm * 8];
            float4 a1 = *(const float4*)&As[buf][k][tm * 8 + 4];
            F4U2 b0, b1;
            b0.f4 = *(const float4*)&Bs[buf][k][tn * 8];
            b1.f4 = *(const float4*)&Bs[buf][k][tn * 8 + 4];
            unsigned long long bp[4] = {b0.u2[0], b0.u2[1], b1.u2[0], b1.u2[1]};
            float av[8] = {a0.x, a0.y, a0.z, a0.w, a1.x, a1.y, a1.z, a1.w};
#pragma unroll
            for (int i = 0; i < 8; i++) {
                unsigned long long ad = dup_f32x2(av[i]);
#pragma unroll
                for (int p = 0; p < 4; p++)
                    fma_f32x2(acc2[i][p], ad, bp[p]);
            }
        }
        if (more) {
            int nb = buf ^ 1;
            As[nb][lcol + 0][lrow] = an.x;  As[nb][lcol + 1][lrow] = an.y;
            As[nb][lcol + 2][lrow] = an.z;  As[nb][lcol + 3][lrow] = an.w;
            Bs[nb][lcol + 0][lrow] = bn4.x; Bs[nb][lcol + 1][lrow] = bn4.y;
            Bs[nb][lcol + 2][lrow] = bn4.z; Bs[nb][lcol + 3][lrow] = bn4.w;
        }
        __syncthreads();
        buf ^= 1;
    }

    int ncol = bn * BN + tn * 8;
    float4 bias0 = *(const float4*)(bias + ncol);
    float4 bias1 = *(const float4*)(bias + ncol + 4);
#pragma unroll
    for (int i = 0; i < 8; i++) {
        int row = bm * BM + tm * 8 + i;
        float* Cp = C + (size_t)row * N + ncol;
        float a01l, a01h, a23l, a23h, a45l, a45h, a67l, a67h;
        unpack_f32x2(acc2[i][0], a01l, a01h);
        unpack_f32x2(acc2[i][1], a23l, a23h);
        unpack_f32x2(acc2[i][2], a45l, a45h);
        unpack_f32x2(acc2[i][3], a67l, a67h);
        float4 c0, c1;
        c0.x = a01l + bias0.x; c0.y = a01h + bias0.y;
        c0.z = a23l + bias0.z; c0.w = a23h + bias0.w;
        c1.x = a45l + bias1.x; c1.y = a45h + bias1.y;
        c1.z = a67l + bias1.z; c1.w = a67h + bias1.w;
        *(float4*)(Cp)     = c0;
        *(float4*)(Cp + 4) = c1;
    }
}

// ---------------- convert fp32 -> bf16 (hi only) for w_out ----------------
__global__ void convert_bf16_kernel(const float* __restrict__ src,
                                    __nv_bfloat16* __restrict__ hi, int n4) {
    int i = blockIdx.x * blockDim.x + threadIdx.x;
    if (i >= n4) return;
    float4 v = ((const float4*)src)[i];
    __nv_bfloat162* h2 = (__nv_bfloat162*)hi;
    h2[2 * i]     = __nv_bfloat162{__float2bfloat16_rn(v.x), __float2bfloat16_rn(v.y)};
    h2[2 * i + 1] = __nv_bfloat162{__float2bfloat16_rn(v.z), __float2bfloat16_rn(v.w)};
}

// ---------------- bf16 mma.sync logits GEMM (2-term split, cp.async staging) ----------------
// C[2048,32000] = (Ahi + Alo) * Bhi^T + bias
#define LBM 128
#define LBN 128
#define LBK 32
#define LSTR (LBK + 8)                 // padded bf16 row stride (80B rows; 80 % 16 == 0)
#define LSTAGE (LBM * LSTR)            // bf16 elems per stage

static_assert(2 * (2 * LBM * LSTR) * 2 <= 48 * 1024, "static smem over 48KB");

__device__ __forceinline__ void ldsm_x4(unsigned& r0, unsigned& r1, unsigned& r2, unsigned& r3,
                                        unsigned addr) {
    asm volatile("ldmatrix.sync.aligned.m8n8.x4.shared.b16 {%0,%1,%2,%3}, [%4];\n"
                 : "=r"(r0), "=r"(r1), "=r"(r2), "=r"(r3) : "r"(addr));
}
__device__ __forceinline__ void mma_bf16(float& c0, float& c1, float& c2, float& c3,
                                         unsigned a0, unsigned a1, unsigned a2, unsigned a3,
                                         unsigned b0, unsigned b1) {
    asm volatile("mma.sync.aligned.m16n8k16.row.col.f32.bf16.bf16.f32 "
                 "{%0,%1,%2,%3},{%4,%5,%6,%7},{%8,%9},{%0,%1,%2,%3};\n"
                 : "+f"(c0), "+f"(c1), "+f"(c2), "+f"(c3)
                 : "r"(a0), "r"(a1), "r"(a2), "r"(a3), "r"(b0), "r"(b1));
}

__global__ __launch_bounds__(256, 2) void mma_logits_kernel(
    const __nv_bfloat16* __restrict__ A_hi, const __nv_bfloat16* __restrict__ A_lo,
    const __nv_bfloat16* __restrict__ B_hi,
    const float* __restrict__ bias, float* __restrict__ C) {
    __shared__ __align__(16) __nv_bfloat16 As[2][LBM][LSTR];
    __shared__ __align__(16) __nv_bfloat16 Bs[2][LBN][LSTR];

    const int tid = threadIdx.x;
    const int bm = blockIdx.y, bn = blockIdx.x;
    const int warp = tid >> 5, lane = tid & 31;
    const int wm = warp >> 2, wn = warp & 3;      // 2 x 4 warps, tile 64 x 32

    const int lrow = tid >> 1;
    const int lhalf = (tid & 1) * 16;
    const size_t Aoff = (size_t)(bm * LBM + lrow) * HH + lhalf;
    const size_t Boff = (size_t)(bn * LBN + lrow) * HH + lhalf;

    const __nv_bfloat16* Asrc[2] = {A_hi, A_lo};

    float acc[4][4][4];
#pragma unroll
    for (int i = 0; i < 4; i++)
#pragma unroll
        for (int j = 0; j < 4; j++)
#pragma unroll
            for (int c = 0; c < 4; c++) acc[i][j][c] = 0.f;

    const int q = lane >> 3, rr = lane & 7;
    unsigned as_base = (unsigned)__cvta_generic_to_shared(&As[0][0][0]);
    unsigned bs_base = (unsigned)__cvta_generic_to_shared(&Bs[0][0][0]);
    unsigned a_addr0 = as_base + (unsigned)(((wm * 64 + (q & 1) * 8 + rr) * LSTR + (q >> 1) * 8) * 2);
    unsigned b_addr0 = bs_base + (unsigned)(((wn * 32 + (q >> 1) * 8 + rr) * LSTR + (q & 1) * 8) * 2);

    // per-thread cp.async destination offsets (bytes; lrow*80 + {0,32} -> 16B aligned)
    const unsigned st_off = (unsigned)((lrow * LSTR + lhalf) * 2);
    const unsigned a_dst = as_base + st_off;
    const unsigned b_dst = bs_base + st_off;

    // prologue: stage 0 via cp.async
    cp_async16(a_dst,      Asrc[0] + Aoff);
    cp_async16(a_dst + 16, Asrc[0] + Aoff + 8);
    cp_async16(b_dst,      B_hi + Boff);
    cp_async16(b_dst + 16, B_hi + Boff + 8);
    cp_commit();
    cp_wait0();
    __syncthreads();

    const int KTOT = 2 * (HH / LBK);   // 32
    int buf = 0;
    for (int kt = 0; kt < KTOT; kt++) {
        bool more = (kt + 1 < KTOT);
        if (more) {
            int seg = (kt + 1) >> 4;               // 0 or 1
            int kk = ((kt + 1) & 15) * LBK;
            unsigned nboff = (unsigned)((buf ^ 1) * LSTAGE * 2);
            cp_async16(a_dst + nboff,      Asrc[seg] + Aoff + kk);
            cp_async16(a_dst + nboff + 16, Asrc[seg] + Aoff + kk + 8);
            cp_async16(b_dst + nboff,      B_hi + Boff + kk);
            cp_async16(b_dst + nboff + 16, B_hi + Boff + kk + 8);
            cp_commit();
        }
        unsigned bufoff = (unsigned)(buf * LSTAGE * 2);
#pragma unroll
        for (int ks = 0; ks < 2; ks++) {
            unsigned af[4][4], bfr[2][4];
#pragma unroll
            for (int mf = 0; mf < 4; mf++)
                ldsm_x4(af[mf][0], af[mf][1], af[mf][2], af[mf][3],
                        a_addr0 + bufoff + (unsigned)(mf * 16 * LSTR * 2 + ks * 32));
#pragma unroll
            for (int nf2 = 0; nf2 < 2; nf2++)
                ldsm_x4(bfr[nf2][0], bfr[nf2][1], bfr[nf2][2], bfr[nf2][3],
                        b_addr0 + bufoff + (unsigned)(nf2 * 16 * LSTR * 2 + ks * 32));
#pragma unroll
            for (int mf = 0; mf < 4; mf++)
#pragma unroll
                for (int nf = 0; nf < 4; nf++)
                    mma_bf16(acc[mf][nf][0], acc[mf][nf][1], acc[mf][nf][2], acc[mf][nf][3],
                             af[mf][0], af[mf][1], af[mf][2], af[mf][3],
                             bfr[nf >> 1][(nf & 1) * 2], bfr[nf >> 1][(nf & 1) * 2 + 1]);
        }
        if (more) cp_wait0();
        __syncthreads();
        buf ^= 1;
    }

    const int rbase = bm * LBM + wm * 64 + (lane >> 2);
    const int cb = bn * LBN + wn * 32 + 2 * (lane & 3);
#pragma unroll
    for (int mf = 0; mf < 4; mf++) {
#pragma unroll
        for (int nf = 0; nf < 4; nf++) {
            int col = cb + nf * 8;
            float bx = bias[col], by = bias[col + 1];
            int r0 = rbase + mf * 16;
            float2 v0 = {acc[mf][nf][0] + bx, acc[mf][nf][1] + by};
            float2 v1 = {acc[mf][nf][2] + bx, acc[mf][nf][3] + by};
            *(float2*)(C + (size_t)r0 * VV + col)       = v0;
            *(float2*)(C + (size_t)(r0 + 8) * VV + col) = v1;
        }
    }
}

// ---------------- persistent GRU scan (one launch, 128 co-resident blocks) ----------------
#define GRUBLOCKS 128
#define HPAD 516
__device__ unsigned g_bar_count;               // returns to 0 after every barrier
__device__ volatile unsigned g_bar_gen;        // monotonically increasing generation

__device__ __forceinline__ void grid_barrier_128() {
    __syncthreads();
    if (threadIdx.x == 0) {
        __threadfence();                       // release my block's writes
        unsigned gen = g_bar_gen;              // read BEFORE arriving
        if (atomicAdd(&g_bar_count, 1u) == GRUBLOCKS - 1) {
            g_bar_count = 0;
            __threadfence();                   // count reset visible before release
            g_bar_gen = gen + 1;
        } else {
            // capped spin with backoff: a barrier bug fails with wrong output, not a hang
            for (int s = 0; g_bar_gen == gen && s < 2000000; s++) __nanosleep(20);
        }
        __threadfence();                       // acquire other blocks' writes
    }
    __syncthreads();
}

__global__ __launch_bounds__(256, 1) void gru_persistent_kernel(
    const float* __restrict__ w_hh, const float* __restrict__ b_hh,
    const float* __restrict__ encoder_hidden, float* __restrict__ out_tail) {
    __shared__ float h_s[BB * HPAD];
    __shared__ float hp_s[192];
    const int tid = threadIdx.x;
    const int jbase = blockIdx.x * 4;

    // per-thread invariants for the dot phase (w_hh rows stay L1-resident across steps)
    const int db = tid & 15;            // batch (dot phase)
    const int didx = tid >> 4;          // 0..11 when tid<192 : gate*4 + col
    const int drow = (didx >> 2) * HH + jbase + (didx & 3);
    const float4* w4 = (const float4*)(w_hh + (size_t)drow * HH);
    const float bh = (tid < 192) ? b_hh[drow] : 0.f;

    for (int t = 0; t < TT; t++) {
        const float* h_in = (t == 0) ? encoder_hidden : g_h[t & 1];
        float* h_out = g_h[(t + 1) & 1];

        // load h [16,512] into padded smem (L2-only loads: avoid stale L1 across barrier)
        for (int i = tid; i < BB * (HH / 4); i += 256) {
            int b = i >> 7;
            int k4 = i & 127;
            float4 v = __ldcg(((const float4*)(h_in + b * HH)) + k4);
            ((float4*)(h_s + b * HPAD))[k4] = v;
        }
        __syncthreads();

        if (tid < 192) {
            const float4* h4 = (const float4*)(h_s + db * HPAD);
            float s0 = 0.f, s1 = 0.f, s2 = 0.f, s3 = 0.f;
#pragma unroll 8
            for (int k = 0; k < HH / 4; k++) {
                float4 w = w4[k];
                float4 h = h4[k];
                s0 += w.x * h.x; s1 += w.y * h.y;
                s2 += w.z * h.z; s3 += w.w * h.w;
            }
            hp_s[didx * 16 + db] = (s0 + s1) + (s2 + s3) + bh;
        }
        __syncthreads();

        if (tid < 64) {
            int b = tid & 15;
            int jc = tid >> 4;
            int j = jbase + jc;
            const float* xp = g_xproj + ((size_t)(t * BB + b)) * G3;
            float xr = xp[j], xz = xp[HH + j], xn = xp[2 * HH + j];
            float hr = hp_s[(0 * 4 + jc) * 16 + b];
            float hz = hp_s[(1 * 4 + jc) * 16 + b];
            float hn = hp_s[(2 * 4 + jc) * 16 + b];
            float r = 1.f / (1.f + __expf(-(xr + hr)));
            float z = 1.f / (1.f + __expf(-(xz + hz)));
            float n = tanhf(xn + r * hn);
            float hprev = h_s[b * HPAD + j];
            float hnew = (1.f - z) * n + z * hprev;
            h_out[b * HH + j] = hnew;
            size_t ai = ((size_t)(b * TT + t)) * HH + j;
            __nv_bfloat16 hi = __float2bfloat16_rn(hnew);
            g_Ahi[ai] = hi;
            g_Alo[ai] = __float2bfloat16_rn(hnew - __bfloat162float(hi));
            if (t == TT - 1) out_tail[b * HH + j] = hnew;   // final hidden -> output tail
        }
        grid_barrier_128();   // all reads of buf[t&1] complete before anyone writes it at t+1
    }
}

// ---------------- kernel: row-wise log-softmax ----------------
__global__ void logsoftmax_kernel(const float* __restrict__ logits,
                                  float* __restrict__ out) {
    int r = blockIdx.x;
    const float4* x4 = (const float4*)(logits + (size_t)r * VV);
    float4* o4 = (float4*)(out + (size_t)r * VV);
    int tid = threadIdx.x;
    const int NV4 = VV / 4;

    float m = -INFINITY, s = 0.f;
    for (int c = tid; c < NV4; c += 256) {
        float4 v = x4[c];
        float mn;
        mn = fmaxf(m, v.x); s = s * __expf(m - mn) + __expf(v.x - mn); m = mn;
        mn = fmaxf(m, v.y); s = s * __expf(m - mn) + __expf(v.y - mn); m = mn;
        mn = fmaxf(m, v.z); s = s * __expf(m - mn) + __expf(v.z - mn); m = mn;
        mn = fmaxf(m, v.w); s = s * __expf(m - mn) + __expf(v.w - mn); m = mn;
    }
    __shared__ float ms[256], ss[256];
    ms[tid] = m; ss[tid] = s;
    __syncthreads();
    for (int off = 128; off > 0; off >>= 1) {
        if (tid < off) {
            float m2 = ms[tid + off], s2 = ss[tid + off];
            float mn = fmaxf(ms[tid], m2);
            ss[tid] = ss[tid] * __expf(ms[tid] - mn) + s2 * __expf(m2 - mn);
            ms[tid] = mn;
        }
        __syncthreads();
    }
    float lse = ms[0] + __logf(ss[0]);
    for (int c = tid; c < NV4; c += 256) {
        float4 v = x4[c];
        v.x -= lse; v.y -= lse; v.z -= lse; v.w -= lse;
        o4[c] = v;
    }
}

// ---------------- launcher ----------------
// inputs: 0 encoder_output (unused), 1 encoder_hidden, 2 tgt_tensor, 3 emb,
// 4 w_ih, 5 b_ih, 6 w_hh, 7 b_hh, 8 w_out, 9 b_out
// output: log_probs [16,128,32000] fp32, then hidden [1,16,512] fp32
extern "C" void kernel_launch(void* const* d_in, const int* in_sizes, int n_in,
                              void* d_out, int out_size) {
    const float* encoder_hidden = (const float*)d_in[1];
    const int*   tgt            = (const int*)d_in[2];
    const float* emb            = (const float*)d_in[3];
    const float* w_ih           = (const float*)d_in[4];
    const float* b_ih           = (const float*)d_in[5];
    const float* w_hh           = (const float*)d_in[6];
    const float* b_hh           = (const float*)d_in[7];
    const float* w_out          = (const float*)d_in[8];
    const float* b_out          = (const float*)d_in[9];
    float* out = (float*)d_out;

    float *g_x_p, *g_xproj_p, *g_logits_p;
    __nv_bfloat16 *ahi, *alo, *bhi;
    cudaGetSymbolAddress((void**)&g_x_p, g_x);
    cudaGetSymbolAddress((void**)&g_xproj_p, g_xproj);
    cudaGetSymbolAddress((void**)&g_logits_p, g_logits);
    cudaGetSymbolAddress((void**)&ahi, g_Ahi);
    cudaGetSymbolAddress((void**)&alo, g_Alo);
    cudaGetSymbolAddress((void**)&bhi, g_Bhi);

    // 1. embedding + relu
    embed_relu_kernel<<<BB * TT, 128>>>(tgt, emb);

    // 2. x_proj = x @ w_ih^T + b_ih (fp32 — feeds recurrence)
    gemm_bias_kernel<<<dim3(G3 / BN, (BB * TT) / BM), 256>>>(
        g_x_p, w_ih, b_ih, g_xproj_p, BB * TT, G3, HH);

    // 3. convert w_out to bf16 (hi only; independent of scan)
    {
        int n4 = VV * HH / 4;
        convert_bf16_kernel<<<(n4 + 255) / 256, 256>>>(w_out, bhi, n4);
    }

    // 4. persistent GRU scan (single launch; h0 read + final-hidden write folded in)
    gru_persistent_kernel<<<GRUBLOCKS, 256>>>(
        w_hh, b_hh, encoder_hidden, out + (size_t)BB * TT * VV);

    // 5. logits via tensor cores (2-term bf16 split, cp.async staging)
    mma_logits_kernel<<<dim3(VV / LBN, (BB * TT) / LBM), 256>>>(
        ahi, alo, bhi, b_out, g_logits_p);

    // 6. log_softmax -> output
    logsoftmax_kernel<<<BB * TT, 256>>>(g_logits_p, out);
}